// round 10
// baseline (speedup 1.0000x reference)
#include <cuda_runtime.h>
#include <stdint.h>

// ---------------------------------------------------------------------------
// BoltzmannGateSTE: keep top-k (k = int(n/e)) by |x|, zero the rest.
// R10 = R8 (measured 76.3us) + two fixes:
//   (a) flush also accumulates g_super -> supers_scan (8us) replaced by a
//       single-block final_scan (~2us) that never touches the 4MB hist bulk.
//   (b) fused_p1 grid 1024 -> 1184 (full occupancy, R1-proven config).
//   K1 zero_all:   zero 4MB hist + counters
//   K2 fused_p1:   read x once -> speculative out, stage window elems to
//                  list + 2^20 hist + 1024 supers; LAST block verifies.
//   K3 fb_all:     exact radix-select fallback (no-op unless verify failed)
//   K4 final_scan: single block: scan supers + boundary slice -> exact tbits
//   K5 fixup:      scatter keepers from list (or full re-mask in fallback)
// ---------------------------------------------------------------------------

#define NBINS   (1u << 20)
#define NSUP    1024
#define NCOARSE 4096
#define LISTCAP (1 << 22)      // 4M entries (expected ~1.11M)
#define CAPB    2048           // per-block staging (expected ~941/block)
#define GRID    1024
#define BLK     256
#define STRIDE  (GRID * BLK)
#define GRID2   1184           // fused_p1 grid (148 SMs * 8)
#define STRIDE2 (GRID2 * BLK)
#define FBGRID  444
#define WLO_N   0x3F600000u    // bits(0.875f)
#define WSPAN_N (1u << 20)     // window = exactly 2^20 ulp-groups
#define WHI_N   (WLO_N + WSPAN_N)   // bits(0.9375f)

__device__ __align__(16) unsigned g_fine[NBINS];
__device__ unsigned g_super[NSUP];
__device__ unsigned g_coarse[NCOARSE];
__device__ unsigned g_A;
__device__ unsigned g_listcnt;
__device__ unsigned g_overflow;
__device__ unsigned g_mode;
__device__ unsigned g_krem;
__device__ unsigned g_wlo;
__device__ unsigned g_tbits;
__device__ unsigned g_done1;       // ticket for K2 verification
__device__ unsigned g_fb_cnt;      // fallback grid barrier
__device__ volatile unsigned g_fb_sense;
__device__ uint2    g_list[LISTCAP];

// ---------------- K1: zero scratch (runs each replay) ----------------------
__global__ void zero_all() {
    int idx = blockIdx.x * blockDim.x + threadIdx.x;
    int stride = gridDim.x * blockDim.x;
    uint4 z = make_uint4(0, 0, 0, 0);
    uint4* f4 = (uint4*)g_fine;
    for (unsigned i = idx; i < NBINS / 4; i += stride) f4[i] = z;
    for (int i = idx; i < NCOARSE; i += stride) g_coarse[i] = 0;
    for (int i = idx; i < NSUP; i += stride) g_super[i] = 0;
    if (idx == 0) {
        g_A = 0; g_listcnt = 0; g_overflow = 0; g_mode = 0;
        g_done1 = 0; g_fb_cnt = 0; g_fb_sense = 0;
    }
}

// ---------------- K2: fused streaming pass + last-block verify -------------
__global__ void __launch_bounds__(BLK)
fused_p1(const float4* __restrict__ x, float4* __restrict__ out,
         int n4, int rem, unsigned k)
{
    __shared__ uint2 sbuf[CAPB];          // 16KB staging
    __shared__ unsigned scratch[BLK];     // 1KB reduce
    __shared__ unsigned svar[4];          // 0:scnt 1:sbase
    const int tid = threadIdx.x;
    const int gtid = blockIdx.x * BLK + tid;
    const float* xs = (const float*)x;
    float* outs = (float*)out;

    if (tid == 0) svar[0] = 0;
    __syncthreads();

    unsigned cntHi = 0;
#define DO1(f, eidx, odst) { \
    unsigned raw = __float_as_uint(f); \
    unsigned u = raw & 0x7FFFFFFFu; \
    odst = (u >= WHI_N) ? f : 0.0f; \
    cntHi += (u >= WHI_N); \
    if (u - WLO_N < WSPAN_N) { \
        unsigned p = atomicAdd(&svar[0], 1u); \
        if (p < CAPB) { sbuf[p].x = (eidx); sbuf[p].y = raw; } \
    } \
}
#define DO4(vv, fi) { \
    float4 o; \
    unsigned eb = (unsigned)(fi) * 4u; \
    DO1(vv.x, eb + 0u, o.x); \
    DO1(vv.y, eb + 1u, o.y); \
    DO1(vv.z, eb + 2u, o.z); \
    DO1(vv.w, eb + 3u, o.w); \
    __stcs(&out[fi], o); \
}
    {
        int i = gtid;
        for (; i + STRIDE2 < n4; i += 2 * STRIDE2) {
            float4 v0 = __ldcs(&x[i]);
            float4 v1 = __ldcs(&x[i + STRIDE2]);
            DO4(v0, i);
            DO4(v1, i + STRIDE2);
        }
        for (; i < n4; i += STRIDE2) {
            float4 v = __ldcs(&x[i]);
            DO4(v, i);
        }
    }
#undef DO4
#undef DO1
    if (gtid < rem) {   // scalar tail
        float f = xs[n4 * 4 + gtid];
        unsigned raw = __float_as_uint(f);
        unsigned u = raw & 0x7FFFFFFFu;
        cntHi += (u >= WHI_N);
        outs[n4 * 4 + gtid] = (u >= WHI_N) ? f : 0.0f;
        if (u - WLO_N < WSPAN_N) {
            unsigned p = atomicAdd(&svar[0], 1u);
            if (p < CAPB) { sbuf[p].x = (unsigned)(n4 * 4 + gtid); sbuf[p].y = raw; }
        }
    }

    // block-reduce cntHi; reserve list space
    scratch[tid] = cntHi;
    __syncthreads();
    for (int off = BLK / 2; off > 0; off >>= 1) {
        if (tid < off) scratch[tid] += scratch[tid + off];
        __syncthreads();
    }
    if (tid == 0) {
        if (scratch[0]) atomicAdd(&g_A, scratch[0]);
        unsigned c = svar[0];
        if (c > CAPB) { c = CAPB; g_overflow = 1u; }
        unsigned base = atomicAdd(&g_listcnt, c);
        if (base + c > LISTCAP) g_overflow = 1u;
        svar[0] = c;
        svar[1] = base;
    }
    __syncthreads();
    {   // flush staging -> list + window histogram + super sums
        unsigned c = svar[0], base = svar[1];
        for (unsigned j = tid; j < c; j += BLK) {
            uint2 e = sbuf[j];
            if (base + j < LISTCAP) g_list[base + j] = e;
            unsigned d = (e.y & 0x7FFFFFFFu) - WLO_N;
            atomicAdd(&g_fine[d], 1u);
            atomicAdd(&g_super[d >> 10], 1u);
        }
    }
    // last block out performs verification
    __syncthreads();
    __threadfence();
    if (tid == 0) {
        if (atomicAdd(&g_done1, 1u) == GRID2 - 1u) {
            __threadfence();
            unsigned A = g_A, cnt = g_listcnt, ov = g_overflow;
            unsigned mode = 1u;
            if (!ov && A < k && (k - A) <= cnt) {
                mode = 0u; g_krem = k - A; g_wlo = WLO_N;
            }
            g_mode = mode;
        }
    }
}

// ---------------- K3: exact fallback (no-op when verification passed) ------
__device__ __forceinline__ void fb_bar() {
    __syncthreads();
    if (threadIdx.x == 0) {
        unsigned s = g_fb_sense ^ 1u;
        __threadfence();
        if (atomicAdd(&g_fb_cnt, 1u) == FBGRID - 1u) {
            g_fb_cnt = 0u;
            __threadfence();
            g_fb_sense = s;
        } else {
            while (g_fb_sense != s) __nanosleep(64);
            __threadfence();
        }
    }
    __syncthreads();
}

__global__ void __launch_bounds__(BLK)
fb_all(const float4* __restrict__ x, int n4, int rem, unsigned k)
{
    if (g_mode == 0u) return;
    __shared__ unsigned scratch[BLK];
    const int tid = threadIdx.x;
    const int gtid = blockIdx.x * BLK + tid;
    const int FTOT = FBGRID * BLK;
    const float* xs = (const float*)x;

    // zero stale window hist + supers, build coarse hist (cold path)
    uint4 z = make_uint4(0, 0, 0, 0);
    uint4* f4 = (uint4*)g_fine;
    for (unsigned i = gtid; i < NBINS / 4; i += FTOT) f4[i] = z;
    for (int i = gtid; i < NSUP; i += FTOT) g_super[i] = 0;
    for (int i = gtid; i < n4; i += FTOT) {
        float4 v = x[i];
        atomicAdd(&g_coarse[(__float_as_uint(v.x) & 0x7FFFFFFFu) >> 19], 1u);
        atomicAdd(&g_coarse[(__float_as_uint(v.y) & 0x7FFFFFFFu) >> 19], 1u);
        atomicAdd(&g_coarse[(__float_as_uint(v.z) & 0x7FFFFFFFu) >> 19], 1u);
        atomicAdd(&g_coarse[(__float_as_uint(v.w) & 0x7FFFFFFFu) >> 19], 1u);
    }
    for (int g = gtid; g < rem; g += FTOT)
        atomicAdd(&g_coarse[(__float_as_uint(xs[n4 * 4 + g]) & 0x7FFFFFFFu) >> 19], 1u);
    fb_bar();

    if (blockIdx.x == 0) {   // coarse scan: 16 buckets per thread
        unsigned c[16], sum = 0;
        #pragma unroll
        for (int j = 0; j < 16; j++) { c[j] = g_coarse[tid * 16 + j]; sum += c[j]; }
        scratch[tid] = sum;
        __syncthreads();
        for (int off = 1; off < BLK; off <<= 1) {
            unsigned add = (tid + off < BLK) ? scratch[tid + off] : 0u;
            __syncthreads();
            scratch[tid] += add;
            __syncthreads();
        }
        unsigned cum = (tid < BLK - 1) ? scratch[tid + 1] : 0u;
        #pragma unroll
        for (int j = 15; j >= 0; j--) {
            unsigned prev = cum;
            cum += c[j];
            if (cum >= k && prev < k) {
                g_wlo  = ((unsigned)(tid * 16 + j)) << 19;
                g_krem = k - prev;
            }
        }
    }
    fb_bar();

    // fine hist over [wlo, wlo + 2^19), feeding both g_fine and g_super
    const unsigned wlo = g_wlo;
    for (int i = gtid; i < n4; i += FTOT) {
        float4 v = x[i];
        unsigned u0 = __float_as_uint(v.x) & 0x7FFFFFFFu;
        unsigned u1 = __float_as_uint(v.y) & 0x7FFFFFFFu;
        unsigned u2 = __float_as_uint(v.z) & 0x7FFFFFFFu;
        unsigned u3 = __float_as_uint(v.w) & 0x7FFFFFFFu;
        if (u0 - wlo < (1u << 19)) { atomicAdd(&g_fine[u0 - wlo], 1u); atomicAdd(&g_super[(u0 - wlo) >> 10], 1u); }
        if (u1 - wlo < (1u << 19)) { atomicAdd(&g_fine[u1 - wlo], 1u); atomicAdd(&g_super[(u1 - wlo) >> 10], 1u); }
        if (u2 - wlo < (1u << 19)) { atomicAdd(&g_fine[u2 - wlo], 1u); atomicAdd(&g_super[(u2 - wlo) >> 10], 1u); }
        if (u3 - wlo < (1u << 19)) { atomicAdd(&g_fine[u3 - wlo], 1u); atomicAdd(&g_super[(u3 - wlo) >> 10], 1u); }
    }
    for (int g = gtid; g < rem; g += FTOT) {
        unsigned u = __float_as_uint(xs[n4 * 4 + g]) & 0x7FFFFFFFu;
        if (u - wlo < (1u << 19)) { atomicAdd(&g_fine[u - wlo], 1u); atomicAdd(&g_super[(u - wlo) >> 10], 1u); }
    }
}

// ---------------- K4: single block — scan supers + slice -> exact tbits ----
__device__ void scan1024_desc(const unsigned* __restrict__ src, unsigned krem,
                              unsigned* scratch, unsigned* svar) {
    const int t = threadIdx.x;
    unsigned c0 = src[4 * t], c1 = src[4 * t + 1];
    unsigned c2 = src[4 * t + 2], c3 = src[4 * t + 3];
    scratch[t] = c0 + c1 + c2 + c3;
    __syncthreads();
    for (int off = 1; off < BLK; off <<= 1) {
        unsigned add = (t + off < BLK) ? scratch[t + off] : 0u;
        __syncthreads();
        scratch[t] += add;
        __syncthreads();
    }
    unsigned cum = (t < BLK - 1) ? scratch[t + 1] : 0u;
    unsigned cc[4] = {c0, c1, c2, c3};
    #pragma unroll
    for (int j = 3; j >= 0; j--) {
        unsigned prev = cum;
        cum += cc[j];
        if (cum >= krem && prev < krem) { svar[0] = 4u * t + j; svar[1] = krem - prev; }
    }
    __syncthreads();
}

__global__ void __launch_bounds__(BLK)
final_scan()
{
    __shared__ unsigned scratch[BLK];
    __shared__ unsigned svar[4];
    scan1024_desc(g_super, g_krem, scratch, svar);            // -> super sb
    unsigned sb = svar[0], krem2 = svar[1];
    scan1024_desc(g_fine + sb * 1024u, krem2, scratch, svar); // -> bin
    if (threadIdx.x == 0) g_tbits = g_wlo + sb * 1024u + svar[0];
}

// ---------------- K5: fixup (normal) or full re-mask (fallback) ------------
__global__ void __launch_bounds__(BLK)
fixup(const float4* __restrict__ x, float4* __restrict__ out, int n4, int rem)
{
    const unsigned tb = g_tbits;
    const int gtid = blockIdx.x * BLK + threadIdx.x;
    float* outs = (float*)out;
    const float* xs = (const float*)x;
    if (g_mode == 0u) {
        unsigned cnt = g_listcnt;
        if (cnt > LISTCAP) cnt = LISTCAP;
        for (unsigned j = (unsigned)gtid; j < cnt; j += STRIDE) {
            uint2 e = g_list[j];
            if ((e.y & 0x7FFFFFFFu) >= tb) outs[e.x] = __uint_as_float(e.y);
        }
    } else {
        for (int i = gtid; i < n4; i += STRIDE) {
            float4 v = x[i];
            v.x = ((__float_as_uint(v.x) & 0x7FFFFFFFu) >= tb) ? v.x : 0.0f;
            v.y = ((__float_as_uint(v.y) & 0x7FFFFFFFu) >= tb) ? v.y : 0.0f;
            v.z = ((__float_as_uint(v.z) & 0x7FFFFFFFu) >= tb) ? v.z : 0.0f;
            v.w = ((__float_as_uint(v.w) & 0x7FFFFFFFu) >= tb) ? v.w : 0.0f;
            out[i] = v;
        }
        for (int g = gtid; g < rem; g += STRIDE) {
            float f = xs[n4 * 4 + g];
            outs[n4 * 4 + g] = ((__float_as_uint(f) & 0x7FFFFFFFu) >= tb) ? f : 0.0f;
        }
    }
}

__global__ void copy_all(const float4* __restrict__ x, float4* __restrict__ out, int n4) {
    int idx = blockIdx.x * blockDim.x + threadIdx.x;
    int stride = gridDim.x * blockDim.x;
    for (int i = idx; i < n4; i += stride) out[i] = x[i];
}

extern "C" void kernel_launch(void* const* d_in, const int* in_sizes, int n_in,
                              void* d_out, int out_size) {
    const float* x = (const float*)d_in[0];
    float* out = (float*)d_out;
    int n = in_sizes[0];

    // k = max(1, int(n * (1.0/e))) — bit-exact replication of the Python.
    const double FRACTION = 1.0 / 2.718281828459045235360287;
    long long kll = (long long)((double)n * FRACTION);
    if (kll < 1) kll = 1;

    int n4 = n >> 2;
    int rem = n & 3;

    if (kll >= (long long)n) {
        copy_all<<<GRID, BLK>>>((const float4*)x, (float4*)out, n4);
        return;
    }
    unsigned k = (unsigned)kll;

    zero_all<<<GRID, BLK>>>();
    fused_p1<<<GRID2, BLK>>>((const float4*)x, (float4*)out, n4, rem, k);
    fb_all<<<FBGRID, BLK>>>((const float4*)x, n4, rem, k);
    final_scan<<<1, BLK>>>();
    fixup<<<GRID, BLK>>>((const float4*)x, (float4*)out, n4, rem);
}

// round 11
// speedup vs baseline: 2.9339x; 2.9339x over previous
#include <cuda_runtime.h>
#include <stdint.h>

// ---------------------------------------------------------------------------
// BoltzmannGateSTE: keep top-k (k = int(n/e)) by |x|, zero the rest.
// R11 = R8 structure with a 16x tighter speculative window.
//   Window [0.8984375, 0.90234375) = bits [0x3F660000, +2^16). k-th |x| for
//   this shape is 0.9002 +- 1.6e-4 (1 sigma) -> >=11 sigma margin; exact
//   verification + cold full fallback keep correctness unconditional.
//   ~70K window elems -> tiny hist (256KB), tiny list, tiny fixup.
//   Super counters padded to 128B stride (R10's 4KB-compact super array
//   serialized a few L2 slices -> 174us).
//   K1 zero_all:  ~0.3MB scratch
//   K2 fused_p1:  stream read->speculative write, stage window elems,
//                 fine hist (2^16) + padded supers (256); last block verifies
//   K3 fb_all:    cold exact 3-level radix select + re-mask (self-contained)
//   K4 resolve:   1 block: scan 256 supers + 256-bin slice -> exact tbits
//   K5 fixup:     restore keepers from ~70K-entry list
// ---------------------------------------------------------------------------

#define NBINS   (1u << 16)     // fine bins over the window (1 ulp each)
#define NSUP    256            // supers of 256 bins
#define SUPSTR  32             // super stride in uints (128B anti-contention)
#define NCOARSE 4096
#define LISTCAP (1 << 20)      // 1M entries (expected ~70K)
#define CAPB    512            // per-block staging (expected ~68/block)
#define GRID    1024
#define BLK     256
#define STRIDE  (GRID * BLK)
#define FBGRID  444
#define WLO_N   0x3F660000u    // bits(0.8984375f)
#define WSPAN_N (1u << 16)
#define WHI_N   (WLO_N + WSPAN_N)   // bits(0.90234375f)

__device__ __align__(16) unsigned g_fine[NBINS];
__device__ unsigned g_superp[NSUP * SUPSTR];   // padded supers
__device__ unsigned g_coarse[NCOARSE];
__device__ unsigned g_h2[8];
__device__ unsigned g_A;
__device__ unsigned g_listcnt;
__device__ unsigned g_overflow;
__device__ unsigned g_mode;
__device__ unsigned g_krem;
__device__ unsigned g_tbits;
__device__ unsigned g_sel;         // rank outputs (fallback scans)
__device__ unsigned g_rem2;
__device__ unsigned g_done1;       // K2 verification ticket
__device__ unsigned g_fb_cnt;      // fallback grid barrier
__device__ volatile unsigned g_fb_sense;
__device__ uint2    g_list[LISTCAP];

// ---------------- K1: zero scratch (runs each replay) ----------------------
__global__ void zero_all() {
    int idx = blockIdx.x * blockDim.x + threadIdx.x;
    int stride = gridDim.x * blockDim.x;
    for (unsigned i = idx; i < NBINS; i += stride) g_fine[i] = 0;
    for (int i = idx; i < NSUP * SUPSTR; i += stride) g_superp[i] = 0;
    for (int i = idx; i < NCOARSE; i += stride) g_coarse[i] = 0;
    if (idx < 8) g_h2[idx] = 0;
    if (idx == 0) {
        g_A = 0; g_listcnt = 0; g_overflow = 0; g_mode = 0;
        g_done1 = 0; g_fb_cnt = 0; g_fb_sense = 0;
    }
}

// ---------------- K2: fused streaming pass + last-block verify -------------
__global__ void __launch_bounds__(BLK)
fused_p1(const float4* __restrict__ x, float4* __restrict__ out,
         int n4, int rem, unsigned k)
{
    __shared__ uint2 sbuf[CAPB];          // 4KB staging
    __shared__ unsigned scratch[BLK];     // 1KB reduce
    __shared__ unsigned svar[4];          // 0:scnt 1:sbase
    const int tid = threadIdx.x;
    const int gtid = blockIdx.x * BLK + tid;
    const float* xs = (const float*)x;
    float* outs = (float*)out;

    if (tid == 0) svar[0] = 0;
    __syncthreads();

    unsigned cntHi = 0;
#define DO1(f, eidx, odst) { \
    unsigned raw = __float_as_uint(f); \
    unsigned u = raw & 0x7FFFFFFFu; \
    odst = (u >= WHI_N) ? f : 0.0f; \
    cntHi += (u >= WHI_N); \
    if (u - WLO_N < WSPAN_N) { \
        unsigned p = atomicAdd(&svar[0], 1u); \
        if (p < CAPB) { sbuf[p].x = (eidx); sbuf[p].y = raw; } \
    } \
}
#define DO4(vv, fi) { \
    float4 o; \
    unsigned eb = (unsigned)(fi) * 4u; \
    DO1(vv.x, eb + 0u, o.x); \
    DO1(vv.y, eb + 1u, o.y); \
    DO1(vv.z, eb + 2u, o.z); \
    DO1(vv.w, eb + 3u, o.w); \
    __stcs(&out[fi], o); \
}
    {
        int i = gtid;
        for (; i + STRIDE < n4; i += 2 * STRIDE) {
            float4 v0 = __ldcs(&x[i]);
            float4 v1 = __ldcs(&x[i + STRIDE]);
            DO4(v0, i);
            DO4(v1, i + STRIDE);
        }
        for (; i < n4; i += STRIDE) {
            float4 v = __ldcs(&x[i]);
            DO4(v, i);
        }
    }
#undef DO4
#undef DO1
    if (gtid < rem) {   // scalar tail
        float f = xs[n4 * 4 + gtid];
        unsigned raw = __float_as_uint(f);
        unsigned u = raw & 0x7FFFFFFFu;
        cntHi += (u >= WHI_N);
        outs[n4 * 4 + gtid] = (u >= WHI_N) ? f : 0.0f;
        if (u - WLO_N < WSPAN_N) {
            unsigned p = atomicAdd(&svar[0], 1u);
            if (p < CAPB) { sbuf[p].x = (unsigned)(n4 * 4 + gtid); sbuf[p].y = raw; }
        }
    }

    // block-reduce cntHi; reserve list space
    scratch[tid] = cntHi;
    __syncthreads();
    for (int off = BLK / 2; off > 0; off >>= 1) {
        if (tid < off) scratch[tid] += scratch[tid + off];
        __syncthreads();
    }
    if (tid == 0) {
        if (scratch[0]) atomicAdd(&g_A, scratch[0]);
        unsigned c = svar[0];
        if (c > CAPB) { c = CAPB; g_overflow = 1u; }
        unsigned base = atomicAdd(&g_listcnt, c);
        if (base + c > LISTCAP) g_overflow = 1u;
        svar[0] = c;
        svar[1] = base;
    }
    __syncthreads();
    {   // flush staging -> list + fine hist + padded supers
        unsigned c = svar[0], base = svar[1];
        for (unsigned j = tid; j < c; j += BLK) {
            uint2 e = sbuf[j];
            if (base + j < LISTCAP) g_list[base + j] = e;
            unsigned d = (e.y & 0x7FFFFFFFu) - WLO_N;
            atomicAdd(&g_fine[d], 1u);
            atomicAdd(&g_superp[(d >> 8) * SUPSTR], 1u);
        }
    }
    // last block out performs verification
    __syncthreads();
    __threadfence();
    if (tid == 0) {
        if (atomicAdd(&g_done1, 1u) == GRID - 1u) {
            __threadfence();
            unsigned A = g_A, cnt = g_listcnt, ov = g_overflow;
            unsigned mode = 1u;
            if (!ov && A < k && (k - A) <= cnt) {
                mode = 0u; g_krem = k - A;
            }
            g_mode = mode;
        }
    }
}

// ---------------- K3: cold exact fallback (no-op when verify passed) -------
__device__ __forceinline__ void fb_bar() {
    __syncthreads();
    if (threadIdx.x == 0) {
        unsigned s = g_fb_sense ^ 1u;
        __threadfence();
        if (atomicAdd(&g_fb_cnt, 1u) == FBGRID - 1u) {
            g_fb_cnt = 0u;
            __threadfence();
            g_fb_sense = s;
        } else {
            while (g_fb_sense != s) __nanosleep(64);
            __threadfence();
        }
    }
    __syncthreads();
}

__global__ void __launch_bounds__(BLK)
fb_all(const float4* __restrict__ x, float4* __restrict__ out,
       int n4, int rem, unsigned k)
{
    if (g_mode == 0u) return;
    __shared__ unsigned scratch[BLK];
    const int tid = threadIdx.x;
    const int gtid = blockIdx.x * BLK + tid;
    const int FTOT = FBGRID * BLK;
    const float* xs = (const float*)x;
    float* outs = (float*)out;

    // zero stale scratch
    for (unsigned i = gtid; i < NBINS; i += FTOT) g_fine[i] = 0;
    if (gtid < 8) g_h2[gtid] = 0;
    // level 1: coarse hist (4096 bins of 2^19)
    for (int i = gtid; i < n4; i += FTOT) {
        float4 v = x[i];
        atomicAdd(&g_coarse[(__float_as_uint(v.x) & 0x7FFFFFFFu) >> 19], 1u);
        atomicAdd(&g_coarse[(__float_as_uint(v.y) & 0x7FFFFFFFu) >> 19], 1u);
        atomicAdd(&g_coarse[(__float_as_uint(v.z) & 0x7FFFFFFFu) >> 19], 1u);
        atomicAdd(&g_coarse[(__float_as_uint(v.w) & 0x7FFFFFFFu) >> 19], 1u);
    }
    for (int g = gtid; g < rem; g += FTOT)
        atomicAdd(&g_coarse[(__float_as_uint(xs[n4 * 4 + g]) & 0x7FFFFFFFu) >> 19], 1u);
    fb_bar();

    if (blockIdx.x == 0) {   // scan 4096: 16 per thread
        unsigned c[16], sum = 0;
        #pragma unroll
        for (int j = 0; j < 16; j++) { c[j] = g_coarse[tid * 16 + j]; sum += c[j]; }
        scratch[tid] = sum;
        __syncthreads();
        for (int off = 1; off < BLK; off <<= 1) {
            unsigned add = (tid + off < BLK) ? scratch[tid + off] : 0u;
            __syncthreads();
            scratch[tid] += add;
            __syncthreads();
        }
        unsigned cum = (tid < BLK - 1) ? scratch[tid + 1] : 0u;
        #pragma unroll
        for (int j = 15; j >= 0; j--) {
            unsigned prev = cum;
            cum += c[j];
            if (cum >= k && prev < k) { g_sel = (unsigned)(tid * 16 + j); g_rem2 = k - prev; }
        }
    }
    fb_bar();
    const unsigned base0 = g_sel << 19;
    const unsigned krem1 = g_rem2;

    // level 2: 2^16 bins of width 8 over [base0, base0+2^19)
    for (int i = gtid; i < n4; i += FTOT) {
        float4 v = x[i];
        unsigned u0 = __float_as_uint(v.x) & 0x7FFFFFFFu;
        unsigned u1 = __float_as_uint(v.y) & 0x7FFFFFFFu;
        unsigned u2 = __float_as_uint(v.z) & 0x7FFFFFFFu;
        unsigned u3 = __float_as_uint(v.w) & 0x7FFFFFFFu;
        if (u0 - base0 < (1u << 19)) atomicAdd(&g_fine[(u0 - base0) >> 3], 1u);
        if (u1 - base0 < (1u << 19)) atomicAdd(&g_fine[(u1 - base0) >> 3], 1u);
        if (u2 - base0 < (1u << 19)) atomicAdd(&g_fine[(u2 - base0) >> 3], 1u);
        if (u3 - base0 < (1u << 19)) atomicAdd(&g_fine[(u3 - base0) >> 3], 1u);
    }
    for (int g = gtid; g < rem; g += FTOT) {
        unsigned u = __float_as_uint(xs[n4 * 4 + g]) & 0x7FFFFFFFu;
        if (u - base0 < (1u << 19)) atomicAdd(&g_fine[(u - base0) >> 3], 1u);
    }
    fb_bar();

    if (blockIdx.x == 0) {   // scan 65536: 256 per thread (cold)
        unsigned sum = 0;
        for (int j = 0; j < 256; j++) sum += g_fine[tid * 256 + j];
        scratch[tid] = sum;
        __syncthreads();
        for (int off = 1; off < BLK; off <<= 1) {
            unsigned add = (tid + off < BLK) ? scratch[tid + off] : 0u;
            __syncthreads();
            scratch[tid] += add;
            __syncthreads();
        }
        unsigned above = (tid < BLK - 1) ? scratch[tid + 1] : 0u;
        if (above < krem1 && above + sum >= krem1) {
            unsigned cum = above;
            for (int j = 255; j >= 0; j--) {
                unsigned c = g_fine[tid * 256 + j];
                unsigned prev = cum;
                cum += c;
                if (cum >= krem1 && prev < krem1) { g_sel = (unsigned)(tid * 256 + j); g_rem2 = krem1 - prev; }
            }
        }
    }
    fb_bar();
    const unsigned base1 = base0 + (g_sel << 3);
    const unsigned krem2 = g_rem2;

    // level 3: 8 bins of width 1
    for (int i = gtid; i < n4; i += FTOT) {
        float4 v = x[i];
        unsigned u0 = __float_as_uint(v.x) & 0x7FFFFFFFu;
        unsigned u1 = __float_as_uint(v.y) & 0x7FFFFFFFu;
        unsigned u2 = __float_as_uint(v.z) & 0x7FFFFFFFu;
        unsigned u3 = __float_as_uint(v.w) & 0x7FFFFFFFu;
        if (u0 - base1 < 8u) atomicAdd(&g_h2[u0 - base1], 1u);
        if (u1 - base1 < 8u) atomicAdd(&g_h2[u1 - base1], 1u);
        if (u2 - base1 < 8u) atomicAdd(&g_h2[u2 - base1], 1u);
        if (u3 - base1 < 8u) atomicAdd(&g_h2[u3 - base1], 1u);
    }
    for (int g = gtid; g < rem; g += FTOT) {
        unsigned u = __float_as_uint(xs[n4 * 4 + g]) & 0x7FFFFFFFu;
        if (u - base1 < 8u) atomicAdd(&g_h2[u - base1], 1u);
    }
    fb_bar();
    if (blockIdx.x == 0 && tid == 0) {
        unsigned cum = 0;
        for (int j = 7; j >= 0; j--) {
            unsigned prev = cum;
            cum += g_h2[j];
            if (cum >= krem2 && prev < krem2) g_tbits = base1 + (unsigned)j;
        }
    }
    fb_bar();

    // full exact re-mask
    const unsigned tb = g_tbits;
    for (int i = gtid; i < n4; i += FTOT) {
        float4 v = x[i];
        v.x = ((__float_as_uint(v.x) & 0x7FFFFFFFu) >= tb) ? v.x : 0.0f;
        v.y = ((__float_as_uint(v.y) & 0x7FFFFFFFu) >= tb) ? v.y : 0.0f;
        v.z = ((__float_as_uint(v.z) & 0x7FFFFFFFu) >= tb) ? v.z : 0.0f;
        v.w = ((__float_as_uint(v.w) & 0x7FFFFFFFu) >= tb) ? v.w : 0.0f;
        out[i] = v;
    }
    for (int g = gtid; g < rem; g += FTOT) {
        float f = xs[n4 * 4 + g];
        outs[n4 * 4 + g] = ((__float_as_uint(f) & 0x7FFFFFFFu) >= tb) ? f : 0.0f;
    }
}

// ---------------- K4: single block resolves exact tbits (normal path) ------
__global__ void __launch_bounds__(BLK)
resolve()
{
    if (g_mode != 0u) return;
    __shared__ unsigned scratch[BLK];
    __shared__ unsigned svar[4];
    const int t = threadIdx.x;
    const unsigned krem = g_krem;

    // scan 256 supers (descending)
    unsigned c = g_superp[t * SUPSTR];
    scratch[t] = c;
    __syncthreads();
    for (int off = 1; off < BLK; off <<= 1) {
        unsigned add = (t + off < BLK) ? scratch[t + off] : 0u;
        __syncthreads();
        scratch[t] += add;
        __syncthreads();
    }
    {
        unsigned above = (t < BLK - 1) ? scratch[t + 1] : 0u;
        if (above < krem && above + c >= krem) { svar[0] = (unsigned)t; svar[1] = krem - above; }
    }
    __syncthreads();
    const unsigned sb = svar[0], krem2 = svar[1];

    // scan the 256 fine bins of super sb
    unsigned c2 = g_fine[sb * 256u + t];
    __syncthreads();
    scratch[t] = c2;
    __syncthreads();
    for (int off = 1; off < BLK; off <<= 1) {
        unsigned add = (t + off < BLK) ? scratch[t + off] : 0u;
        __syncthreads();
        scratch[t] += add;
        __syncthreads();
    }
    {
        unsigned above = (t < BLK - 1) ? scratch[t + 1] : 0u;
        if (above < krem2 && above + c2 >= krem2)
            g_tbits = WLO_N + sb * 256u + (unsigned)t;
    }
}

// ---------------- K5: fixup — restore keepers from the list ----------------
__global__ void __launch_bounds__(BLK)
fixup(float* __restrict__ out)
{
    if (g_mode != 0u) return;
    const unsigned tb = g_tbits;
    unsigned cnt = g_listcnt;
    if (cnt > LISTCAP) cnt = LISTCAP;
    const unsigned gtid = blockIdx.x * BLK + threadIdx.x;
    const unsigned stride = gridDim.x * BLK;
    for (unsigned j = gtid; j < cnt; j += stride) {
        uint2 e = g_list[j];
        if ((e.y & 0x7FFFFFFFu) >= tb) out[e.x] = __uint_as_float(e.y);
    }
}

__global__ void copy_all(const float4* __restrict__ x, float4* __restrict__ out, int n4) {
    int idx = blockIdx.x * blockDim.x + threadIdx.x;
    int stride = gridDim.x * blockDim.x;
    for (int i = idx; i < n4; i += stride) out[i] = x[i];
}

extern "C" void kernel_launch(void* const* d_in, const int* in_sizes, int n_in,
                              void* d_out, int out_size) {
    const float* x = (const float*)d_in[0];
    float* out = (float*)d_out;
    int n = in_sizes[0];

    // k = max(1, int(n * (1.0/e))) — bit-exact replication of the Python.
    const double FRACTION = 1.0 / 2.718281828459045235360287;
    long long kll = (long long)((double)n * FRACTION);
    if (kll < 1) kll = 1;

    int n4 = n >> 2;
    int rem = n & 3;

    if (kll >= (long long)n) {
        copy_all<<<GRID, BLK>>>((const float4*)x, (float4*)out, n4);
        return;
    }
    unsigned k = (unsigned)kll;

    zero_all<<<256, BLK>>>();
    fused_p1<<<GRID, BLK>>>((const float4*)x, (float4*)out, n4, rem, k);
    fb_all<<<FBGRID, BLK>>>((const float4*)x, (float4*)out, n4, rem, k);
    resolve<<<1, BLK>>>();
    fixup<<<256, BLK>>>(out);
}